// round 15
// baseline (speedup 1.0000x reference)
#include <cuda_runtime.h>
#include <cuda_fp16.h>
#include <cstdint>

#define B      2
#define CIN    512
#define COUT   512
#define RES    256
#define WDIM   512
#define GRIDN  8
#define PATCH  32
#define NP     (B*GRIDN)

// ---------------- scratch (static device globals; no allocation) ----------------
__device__ __align__(128) __half g_xmt[(size_t)NP * RES * PATCH * CIN]; // [p][h][wp][c]
__device__ __align__(128) __half g_wt [(size_t)9 * COUT * CIN];         // [tap][cout][cin]
__device__ float g_styles[B * 3 * CIN];
__device__ float g_invstd[B * CIN * GRIDN];
__device__ float g_demod[COUT];

// ================= helpers ======================================================
__device__ __forceinline__ uint32_t smem_to_u32(const void* p) {
    uint32_t a;
    asm("{ .reg .u64 t; cvta.to.shared.u64 t, %1; cvt.u32.u64 %0, t; }" : "=r"(a) : "l"(p));
    return a;
}
__device__ __forceinline__ void cp_async16(uint32_t dst, const void* src, int sz) {
    asm volatile("cp.async.cg.shared.global [%0], [%1], 16, %2;"
                 :: "r"(dst), "l"(src), "r"(sz));
}
__device__ __forceinline__ void ldsm_x4(uint32_t* r, uint32_t addr) {
    asm volatile("ldmatrix.sync.aligned.m8n8.x4.shared.b16 {%0,%1,%2,%3}, [%4];"
                 : "=r"(r[0]), "=r"(r[1]), "=r"(r[2]), "=r"(r[3]) : "r"(addr));
}
__device__ __forceinline__ void mma_f16(float* d, const uint32_t* a, const uint32_t* b) {
    asm volatile("mma.sync.aligned.m16n8k16.row.col.f32.f16.f16.f32 "
                 "{%0,%1,%2,%3}, {%4,%5,%6,%7}, {%8,%9}, {%0,%1,%2,%3};"
                 : "+f"(d[0]), "+f"(d[1]), "+f"(d[2]), "+f"(d[3])
                 : "r"(a[0]), "r"(a[1]), "r"(a[2]), "r"(a[3]), "r"(b[0]), "r"(b[1]));
}

// ================= small kernels ================================================
__global__ void styles_kernel(const float* __restrict__ w, const float* __restrict__ wctx,
                              const float* __restrict__ aw, const float* __restrict__ ab) {
    int b = blockIdx.x / 3, s = blockIdx.x % 3;
    const float* src = (s == 0) ? (wctx + (b*2 + 0)*WDIM)
                     : (s == 1) ? (w + b*WDIM)
                                : (wctx + (b*2 + 1)*WDIM);
    __shared__ float sv[WDIM];
    for (int i = threadIdx.x; i < WDIM; i += blockDim.x) sv[i] = src[i];
    __syncthreads();
    for (int c = threadIdx.x; c < CIN; c += blockDim.x) {
        const float* row = aw + (size_t)c * WDIM;
        float acc = 0.f;
        #pragma unroll 8
        for (int d = 0; d < WDIM; d++) acc += sv[d] * row[d];
        g_styles[(b*3 + s)*CIN + c] = acc * 0.04419417382415922f + ab[c];
    }
}

// weight transform [cout][cin][9] -> [tap][cout][cin] (fp16) + fused demod
__global__ void wtrans_kernel(const float* __restrict__ wt) {
    __shared__ float sm[CIN * 9];
    __shared__ float red[256];
    int co = blockIdx.x, tid = threadIdx.x;
    const float* row = wt + (size_t)co * CIN * 9;
    float acc = 0.f;
    for (int i = tid; i < CIN * 9; i += 256) { float v = row[i]; sm[i] = v; acc += v * v; }
    red[tid] = acc;
    __syncthreads();
    for (int off = 128; off > 0; off >>= 1) {
        if (tid < off) red[tid] += red[tid + off];
        __syncthreads();
    }
    if (tid == 0) g_demod[co] = rsqrtf(red[0] + 1e-8f);
    for (int tap = 0; tap < 9; tap++)
        for (int ci = tid; ci < CIN; ci += 256)
            g_wt[((size_t)tap * COUT + co) * CIN + ci] = __float2half_rn(sm[ci * 9 + tap]);
}

// per-patch std (ddof=1) — warp-shuffle reduction
__global__ void std_kernel(const float* __restrict__ x) {
    int id = blockIdx.x;                    // ((b*512 + c)*8 + g)
    int g = id & 7, c = (id >> 3) & 511, b = id >> 12;
    const float* base = x + (((size_t)(b*CIN + c)) * RES) * RES + g * PATCH;
    int h = threadIdx.x;
    const float4* row = (const float4*)(base + (size_t)h * RES);
    float s = 0.f, q = 0.f;
    #pragma unroll
    for (int i = 0; i < PATCH/4; i++) {
        float4 v = row[i];
        s += v.x + v.y + v.z + v.w;
        q += v.x*v.x + v.y*v.y + v.z*v.z + v.w*v.w;
    }
    #pragma unroll
    for (int o = 16; o > 0; o >>= 1) {
        s += __shfl_xor_sync(0xFFFFFFFFu, s, o);
        q += __shfl_xor_sync(0xFFFFFFFFu, q, o);
    }
    __shared__ float ss[8], sq[8];
    if ((h & 31) == 0) { ss[h >> 5] = s; sq[h >> 5] = q; }
    __syncthreads();
    if (h == 0) {
        float S = 0.f, Q = 0.f;
        #pragma unroll
        for (int i = 0; i < 8; i++) { S += ss[i]; Q += sq[i]; }
        const float n = (float)(RES * PATCH);
        float var = (Q - S*S/n) / (n - 1.f);
        if (var < 0.f) var = 0.f;
        g_invstd[id] = 1.f / (sqrtf(var) + 1e-8f);
    }
}

// normalize + style lerp + transpose to [p][h][wp][c] (fp16)
// 64-channel blocks -> 128B-contiguous writes (16 lanes x uint2)
#define MOD_SMEM (64 * 257 * 4)   // 65,792 B dynamic
__global__ void modulate_kernel(const float* __restrict__ x, const int* __restrict__ lb) {
    extern __shared__ float sm[];           // [64][257]
    __shared__ float st_s[3][64];
    __shared__ float inv_s[64][8];
    int h = blockIdx.x, cc = blockIdx.y, b = blockIdx.z;
    int c0 = cc * 64;
    int tid = threadIdx.x;
    int w = tid;
    if (tid < 192) st_s[tid >> 6][tid & 63] = g_styles[(b*3 + (tid >> 6))*CIN + c0 + (tid & 63)];
    {   // 512 invstd entries, 2 per thread
        int c = tid >> 2, g2 = (tid & 3) * 2;
        inv_s[c][g2    ] = g_invstd[(b*CIN + c0 + c)*GRIDN + g2    ];
        inv_s[c][g2 + 1] = g_invstd[(b*CIN + c0 + c)*GRIDN + g2 + 1];
    }
    float center = (float)(lb[b] * PATCH);
    float t = ((float)w + 0.5f - center) * (1.f / 256.f);   // D = 256
    t = fminf(fmaxf(t, -1.f), 1.f);
    float a = fminf(fmaxf(-t, 0.f), 1.f);
    float r = fminf(fmaxf( t, 0.f), 1.f);
    float m = 1.f - a - r;
    int g = w >> 5;
    __syncthreads();
    const float* xrow = x + (((size_t)(b*CIN + c0)) * RES + h) * RES;
    #pragma unroll 8
    for (int i = 0; i < 64; i++) {
        float sc = a * st_s[0][i] + m * st_s[1][i] + r * st_s[2][i];
        sm[i*257 + w] = xrow[(size_t)i * RES * RES + w] * inv_s[i][g] * sc;
    }
    __syncthreads();
    #pragma unroll
    for (int u = tid; u < 4096; u += 256) {
        int w2 = u >> 4, q = u & 15;        // 16 lanes -> 128B contiguous
        int p = b*GRIDN + (w2 >> 5), wp = w2 & 31;
        __half2 o0 = __floats2half2_rn(sm[(q*4+0)*257 + w2], sm[(q*4+1)*257 + w2]);
        __half2 o1 = __floats2half2_rn(sm[(q*4+2)*257 + w2], sm[(q*4+3)*257 + w2]);
        uint2 pk = make_uint2(*(uint32_t*)&o0, *(uint32_t*)&o1);
        *(uint2*)(g_xmt + ((((size_t)p * RES + h)) * PATCH + wp) * CIN + c0 + q*4) = pk;
    }
}

// ================= fp16 mma.sync conv (A-halo reuse across taps) =================
// CTA: 128 M (4h x 32wp) x 128 N (cout); 256 thr = 2x4 warps of 64x32
// Outer: 8 cin-blocks of 64; per cb ONE haloed A tile (6h x 34w) serves all 9 taps.
// A double-buffered (2 x 26KB), B triple-buffered (3 x 16KB); 2 CTAs/SM.
#define A_BUF_BYTES 26624          // 208 rows x 128B (204 used)
#define OFF_B       53248          // after 2 A buffers
#define B_STAGE     16384
#define CONV_SMEM   102400
#define NPHASE      72             // 8 cb x 9 taps

__global__ __launch_bounds__(256, 2) void conv_kernel(
    const float* __restrict__ noise, const float* __restrict__ ns_ptr,
    const float* __restrict__ bias,  float* __restrict__ out)
{
    extern __shared__ __align__(1024) char smem[];
    const uint32_t sb = smem_to_u32(smem);
    const int tid  = threadIdx.x;
    const int wid  = tid >> 5, lane = tid & 31;
    const int wm   = wid & 1,  wn   = wid >> 1;   // 2x4 warp grid (64m x 32n tiles)
    const int sIdx = blockIdx.y;                  // 0..1023
    const int p    = sIdx >> 6, hblk = sIdx & 63;
    const int h0   = hblk * 4;
    const int b    = p >> 3, g = p & 7;
    const int coBase = blockIdx.x * 128;

    const __half* xm_p = g_xmt + (size_t)p * RES * PATCH * CIN;
    const int jj = tid & 7;                        // 16B column (8 halfs)
    const int r0 = tid >> 3;                       // 0..31

    // A halo loader: 204 rows = 6 hs x 34 ws, 128B each (64 cin)
    auto load_A = [&](int cb, int buf) {
        const uint32_t abase = sb + buf * A_BUF_BYTES;
        #pragma unroll
        for (int it = 0; it < 7; it++) {
            int rr = r0 + 32*it;
            if (rr < 204) {
                int hh = rr / 34, ww = rr - hh*34;
                int hs = h0 - 1 + hh, ws = ww - 1;
                bool ok = ((unsigned)hs < 256u) && ((unsigned)ws < 32u);
                const __half* src = xm_p + (ok ? (((size_t)hs*PATCH + ws)*CIN + cb*64 + jj*8) : 0);
                uint32_t off = (uint32_t)(rr*128 + ((jj*16) ^ ((rr & 7) << 4)));
                cp_async16(abase + off, src, ok ? 16 : 0);
            }
        }
    };
    // B loader: phase j -> tap j%9, cb j/9; 128 rows x 128B into stage st
    auto load_B = [&](int j, int st) {
        const int cb = j / 9, tap = j - cb*9;
        const uint32_t sbase = sb + OFF_B + st * B_STAGE;
        #pragma unroll
        for (int k = 0; k < 4; k++) {
            int n = r0 + 32*k;
            const __half* src = g_wt + ((size_t)(tap*COUT + coBase + n))*CIN + cb*64 + jj*8;
            uint32_t off = (uint32_t)(n*128 + ((jj*16) ^ ((n & 7) << 4)));
            cp_async16(sbase + off, src, 16);
        }
    };

    float acc[4][4][4];
    #pragma unroll
    for (int mt = 0; mt < 4; mt++)
        #pragma unroll
        for (int nt = 0; nt < 4; nt++)
            #pragma unroll
            for (int q = 0; q < 4; q++) acc[mt][nt][q] = 0.f;

    // prologue: G1 = {A0, B0}; G2 = {B1}
    load_A(0, 0);
    load_B(0, 0);
    asm volatile("cp.async.commit_group;" ::: "memory");
    load_B(1, 1);
    asm volatile("cp.async.commit_group;" ::: "memory");

    // ldmatrix decompositions (round-8 proven mappings)
    const int rA  = (lane & 7) + ((lane >> 3) & 1) * 8;   // A: row-within-16
    const int hiA = (lane >> 4) << 4;                      // A: 16B k-half select
    const int rB  = ((lane >> 4) << 3) + (lane & 7);       // B: row-within-16
    const int khB = ((lane >> 3) & 1) << 4;                // B: 16B k-half select

    int stC = 0, stL = 2, bufA = 0;
    for (int j = 0; j < NPHASE; j++) {
        const int cb = j / 9, t = j - cb*9;
        const int dy = t / 3 - 1, dx = t - (t/3)*3 - 1;

        asm volatile("cp.async.wait_group 1;" ::: "memory");
        __syncthreads();
        if (j + 2 < NPHASE) load_B(j + 2, stL);
        if (t == 7 && cb + 1 < 8) load_A(cb + 1, bufA ^ 1);
        asm volatile("cp.async.commit_group;" ::: "memory");   // exactly 1 group/phase

        const uint32_t aBuf = sb + bufA * A_BUF_BYTES;
        const uint32_t sB   = sb + OFF_B + stC * B_STAGE;

        // per-fragment halo row base (lane row = base + rA folded in)
        int arow[4];
        #pragma unroll
        for (int mt = 0; mt < 4; mt++)
            arow[mt] = (wm*2 + (mt >> 1) + dy + 1)*34 + (mt & 1)*16 + dx + 1 + rA;

        #pragma unroll
        for (int ks = 0; ks < 4; ks++) {           // 4 k-steps of 16 halfs
            uint32_t a[4][4];
            #pragma unroll
            for (int mt = 0; mt < 4; mt++) {
                uint32_t kb = (uint32_t)(ks*32 + hiA);
                ldsm_x4(a[mt], aBuf + arow[mt]*128 + (kb ^ ((arow[mt] & 7) << 4)));
            }
            uint32_t bb[2][4];                     // [np]{rl/kh0, rl/kh1, rh/kh0, rh/kh1}
            #pragma unroll
            for (int np = 0; np < 2; np++) {
                int row = wn*32 + np*16 + rB;
                uint32_t kb = (uint32_t)(ks*32 + khB);
                ldsm_x4(bb[np], sB + row*128 + (kb ^ ((row & 7) << 4)));
            }
            #pragma unroll
            for (int nt = 0; nt < 4; nt++)
                #pragma unroll
                for (int mt = 0; mt < 4; mt++)
                    mma_f16(acc[mt][nt], a[mt], &bb[nt >> 1][(nt & 1) * 2]);
        }
        stC = (stC == 2) ? 0 : stC + 1;
        stL = (stL == 2) ? 0 : stL + 1;
        if (t == 8) bufA ^= 1;
    }

    __syncthreads();   // all compute done before spad overwrites smem

    // ---- epilogue: transpose via padded smem, coalesced stores ------------------
    float* spad = (float*)smem;                    // [128 n][129 m] floats (66KB)
    #pragma unroll
    for (int mt = 0; mt < 4; mt++)
        #pragma unroll
        for (int nt = 0; nt < 4; nt++) {
            int m0 = wm*64 + mt*16 + (lane >> 2);
            int n0 = wn*32 + nt*8 + 2*(lane & 3);
            spad[(n0    )*129 + m0    ] = acc[mt][nt][0];
            spad[(n0 + 1)*129 + m0    ] = acc[mt][nt][1];
            spad[(n0    )*129 + m0 + 8] = acc[mt][nt][2];
            spad[(n0 + 1)*129 + m0 + 8] = acc[mt][nt][3];
        }
    __syncthreads();
    {
        const float nsv = *ns_ptr;
        float nz[4];
        #pragma unroll
        for (int hh = 0; hh < 4; hh++)
            nz[hh] = noise[((size_t)b*RES + h0 + hh)*RES + g*PATCH + lane] * nsv;
        #pragma unroll
        for (int nn = 0; nn < 16; nn++) {
            int n  = wid*16 + nn;
            int co = coBase + n;
            float dm = g_demod[co], bs = bias[co];
            #pragma unroll
            for (int hh = 0; hh < 4; hh++) {
                float v = spad[n*129 + hh*32 + lane];
                v = v * dm + nz[hh] + bs;
                v = (v >= 0.f) ? v : 0.2f * v;
                out[(((size_t)(b*COUT + co))*RES + h0 + hh)*RES + g*PATCH + lane]
                    = v * 1.4142135623730951f;
            }
        }
    }
}

// ---------------- launch ---------------------------------------------------------
extern "C" void kernel_launch(void* const* d_in, const int* in_sizes, int n_in,
                              void* d_out, int out_size) {
    const float* x      = (const float*)d_in[0];
    const float* w      = (const float*)d_in[1];
    const float* wctx   = (const float*)d_in[2];
    const float* weight = (const float*)d_in[3];
    const float* aw     = (const float*)d_in[4];
    const float* ab     = (const float*)d_in[5];
    const float* bias   = (const float*)d_in[6];
    const float* ns     = (const float*)d_in[7];
    const float* noise  = (const float*)d_in[8];
    const int*   lb     = (const int*)d_in[9];
    float* out = (float*)d_out;

    cudaFuncSetAttribute(conv_kernel, cudaFuncAttributeMaxDynamicSharedMemorySize, CONV_SMEM);
    cudaFuncSetAttribute(modulate_kernel, cudaFuncAttributeMaxDynamicSharedMemorySize, MOD_SMEM);

    styles_kernel  <<<6, 256>>>(w, wctx, aw, ab);
    wtrans_kernel  <<<COUT, 256>>>(weight);
    std_kernel     <<<B*CIN*GRIDN, 256>>>(x);
    modulate_kernel<<<dim3(RES, CIN/64, B), 256, MOD_SMEM>>>(x, lb);
    conv_kernel    <<<dim3(4, 1024), 256, CONV_SMEM>>>(noise, ns, bias, out);
}

// round 16
// speedup vs baseline: 1.0197x; 1.0197x over previous
#include <cuda_runtime.h>
#include <cuda_fp16.h>
#include <cstdint>

#define B      2
#define CIN    512
#define COUT   512
#define RES    256
#define WDIM   512
#define GRIDN  8
#define PATCH  32
#define NP     (B*GRIDN)

// ---------------- scratch (static device globals; no allocation) ----------------
__device__ __align__(128) __half g_xmt[(size_t)NP * RES * PATCH * CIN]; // [p][h][wp][c]
__device__ __align__(128) __half g_wt [(size_t)9 * COUT * CIN];         // [tap][cout][cin]
__device__ float g_styles[B * 3 * CIN];
__device__ float g_invstd[B * CIN * GRIDN];
__device__ float g_demod[COUT];

// ================= helpers ======================================================
__device__ __forceinline__ uint32_t smem_to_u32(const void* p) {
    uint32_t a;
    asm("{ .reg .u64 t; cvta.to.shared.u64 t, %1; cvt.u32.u64 %0, t; }" : "=r"(a) : "l"(p));
    return a;
}
__device__ __forceinline__ void cp_async16(uint32_t dst, const void* src, int sz) {
    asm volatile("cp.async.cg.shared.global [%0], [%1], 16, %2;"
                 :: "r"(dst), "l"(src), "r"(sz));
}
__device__ __forceinline__ void ldsm_x4(uint32_t* r, uint32_t addr) {
    asm volatile("ldmatrix.sync.aligned.m8n8.x4.shared.b16 {%0,%1,%2,%3}, [%4];"
                 : "=r"(r[0]), "=r"(r[1]), "=r"(r[2]), "=r"(r[3]) : "r"(addr));
}
__device__ __forceinline__ void mma_f16(float* d, const uint32_t* a, const uint32_t* b) {
    asm volatile("mma.sync.aligned.m16n8k16.row.col.f32.f16.f16.f32 "
                 "{%0,%1,%2,%3}, {%4,%5,%6,%7}, {%8,%9}, {%0,%1,%2,%3};"
                 : "+f"(d[0]), "+f"(d[1]), "+f"(d[2]), "+f"(d[3])
                 : "r"(a[0]), "r"(a[1]), "r"(a[2]), "r"(a[3]), "r"(b[0]), "r"(b[1]));
}

// ================= small kernels ================================================
__global__ void styles_kernel(const float* __restrict__ w, const float* __restrict__ wctx,
                              const float* __restrict__ aw, const float* __restrict__ ab) {
    int b = blockIdx.x / 3, s = blockIdx.x % 3;
    const float* src = (s == 0) ? (wctx + (b*2 + 0)*WDIM)
                     : (s == 1) ? (w + b*WDIM)
                                : (wctx + (b*2 + 1)*WDIM);
    __shared__ float sv[WDIM];
    for (int i = threadIdx.x; i < WDIM; i += blockDim.x) sv[i] = src[i];
    __syncthreads();
    for (int c = threadIdx.x; c < CIN; c += blockDim.x) {
        const float* row = aw + (size_t)c * WDIM;
        float acc = 0.f;
        #pragma unroll 8
        for (int d = 0; d < WDIM; d++) acc += sv[d] * row[d];
        g_styles[(b*3 + s)*CIN + c] = acc * 0.04419417382415922f + ab[c];
    }
}

// weight transform [cout][cin][9] -> [tap][cout][cin] (fp16) + fused demod
__global__ void wtrans_kernel(const float* __restrict__ wt) {
    __shared__ float sm[CIN * 9];
    __shared__ float red[256];
    int co = blockIdx.x, tid = threadIdx.x;
    const float* row = wt + (size_t)co * CIN * 9;
    float acc = 0.f;
    for (int i = tid; i < CIN * 9; i += 256) { float v = row[i]; sm[i] = v; acc += v * v; }
    red[tid] = acc;
    __syncthreads();
    for (int off = 128; off > 0; off >>= 1) {
        if (tid < off) red[tid] += red[tid + off];
        __syncthreads();
    }
    if (tid == 0) g_demod[co] = rsqrtf(red[0] + 1e-8f);
    for (int tap = 0; tap < 9; tap++)
        for (int ci = tid; ci < CIN; ci += 256)
            g_wt[((size_t)tap * COUT + co) * CIN + ci] = __float2half_rn(sm[ci * 9 + tap]);
}

// per-patch std (ddof=1) — warp-shuffle reduction
__global__ void std_kernel(const float* __restrict__ x) {
    int id = blockIdx.x;                    // ((b*512 + c)*8 + g)
    int g = id & 7, c = (id >> 3) & 511, b = id >> 12;
    const float* base = x + (((size_t)(b*CIN + c)) * RES) * RES + g * PATCH;
    int h = threadIdx.x;
    const float4* row = (const float4*)(base + (size_t)h * RES);
    float s = 0.f, q = 0.f;
    #pragma unroll
    for (int i = 0; i < PATCH/4; i++) {
        float4 v = row[i];
        s += v.x + v.y + v.z + v.w;
        q += v.x*v.x + v.y*v.y + v.z*v.z + v.w*v.w;
    }
    #pragma unroll
    for (int o = 16; o > 0; o >>= 1) {
        s += __shfl_xor_sync(0xFFFFFFFFu, s, o);
        q += __shfl_xor_sync(0xFFFFFFFFu, q, o);
    }
    __shared__ float ss[8], sq[8];
    if ((h & 31) == 0) { ss[h >> 5] = s; sq[h >> 5] = q; }
    __syncthreads();
    if (h == 0) {
        float S = 0.f, Q = 0.f;
        #pragma unroll
        for (int i = 0; i < 8; i++) { S += ss[i]; Q += sq[i]; }
        const float n = (float)(RES * PATCH);
        float var = (Q - S*S/n) / (n - 1.f);
        if (var < 0.f) var = 0.f;
        g_invstd[id] = 1.f / (sqrtf(var) + 1e-8f);
    }
}

// normalize + style lerp + transpose to [p][h][wp][c] (fp16); styles/invstd preloaded
// (round-14 proven version: 32-channel blocks, 33KB static smem, occ ~71%)
__global__ void modulate_kernel(const float* __restrict__ x, const int* __restrict__ lb) {
    __shared__ float sm[32][257];
    __shared__ float st_s[3][32];
    __shared__ float inv_s[32][8];
    int h = blockIdx.x, cc = blockIdx.y, b = blockIdx.z;
    int c0 = cc * 32;
    int tid = threadIdx.x;
    int w = tid;
    if (tid < 96) st_s[tid >> 5][tid & 31] = g_styles[(b*3 + (tid >> 5))*CIN + c0 + (tid & 31)];
    { int c = tid >> 3, gg = tid & 7;
      inv_s[c][gg] = g_invstd[(b*CIN + c0 + c)*GRIDN + gg]; }
    float center = (float)(lb[b] * PATCH);
    float t = ((float)w + 0.5f - center) * (1.f / 256.f);   // D = 256
    t = fminf(fmaxf(t, -1.f), 1.f);
    float a = fminf(fmaxf(-t, 0.f), 1.f);
    float r = fminf(fmaxf( t, 0.f), 1.f);
    float m = 1.f - a - r;
    int g = w >> 5;
    __syncthreads();
    const float* xrow = x + (((size_t)(b*CIN + c0)) * RES + h) * RES;
    #pragma unroll 8
    for (int i = 0; i < 32; i++) {
        float sc = a * st_s[0][i] + m * st_s[1][i] + r * st_s[2][i];
        sm[i][w] = xrow[(size_t)i * RES * RES + w] * inv_s[i][g] * sc;
    }
    __syncthreads();
    #pragma unroll
    for (int u = tid; u < 2048; u += 256) {
        int w2 = u >> 3, q = u & 7;
        int p = b*GRIDN + (w2 >> 5), wp = w2 & 31;
        __half2 o0 = __floats2half2_rn(sm[q*4+0][w2], sm[q*4+1][w2]);
        __half2 o1 = __floats2half2_rn(sm[q*4+2][w2], sm[q*4+3][w2]);
        uint2 pk = make_uint2(*(uint32_t*)&o0, *(uint32_t*)&o1);
        *(uint2*)(g_xmt + ((((size_t)p * RES + h)) * PATCH + wp) * CIN + c0 + q*4) = pk;
    }
}

// ================= fp16 mma.sync conv (A-halo reuse across taps) =================
// CTA: 128 M (4h x 32wp) x 128 N (cout); 256 thr = 2x4 warps of 64x32
// Outer: 8 cin-blocks of 64; per cb ONE haloed A tile (6h x 34w) serves all 9 taps.
// A double-buffered (2 x 26KB), B triple-buffered (3 x 16KB); 2 CTAs/SM.
#define A_BUF_BYTES 26624          // 208 rows x 128B (204 used)
#define OFF_B       53248          // after 2 A buffers
#define B_STAGE     16384
#define CONV_SMEM   102400
#define NPHASE      72             // 8 cb x 9 taps

__global__ __launch_bounds__(256, 2) void conv_kernel(
    const float* __restrict__ noise, const float* __restrict__ ns_ptr,
    const float* __restrict__ bias,  float* __restrict__ out)
{
    extern __shared__ __align__(1024) char smem[];
    const uint32_t sb = smem_to_u32(smem);
    const int tid  = threadIdx.x;
    const int wid  = tid >> 5, lane = tid & 31;
    const int wm   = wid & 1,  wn   = wid >> 1;   // 2x4 warp grid (64m x 32n tiles)
    const int sIdx = blockIdx.y;                  // 0..1023
    const int p    = sIdx >> 6, hblk = sIdx & 63;
    const int h0   = hblk * 4;
    const int b    = p >> 3, g = p & 7;
    const int coBase = blockIdx.x * 128;

    const __half* xm_p = g_xmt + (size_t)p * RES * PATCH * CIN;
    const int jj = tid & 7;                        // 16B column (8 halfs)
    const int r0 = tid >> 3;                       // 0..31

    // A halo loader: 204 rows = 6 hs x 34 ws, 128B each (64 cin)
    auto load_A = [&](int cb, int buf) {
        const uint32_t abase = sb + buf * A_BUF_BYTES;
        #pragma unroll
        for (int it = 0; it < 7; it++) {
            int rr = r0 + 32*it;
            if (rr < 204) {
                int hh = rr / 34, ww = rr - hh*34;
                int hs = h0 - 1 + hh, ws = ww - 1;
                bool ok = ((unsigned)hs < 256u) && ((unsigned)ws < 32u);
                const __half* src = xm_p + (ok ? (((size_t)hs*PATCH + ws)*CIN + cb*64 + jj*8) : 0);
                uint32_t off = (uint32_t)(rr*128 + ((jj*16) ^ ((rr & 7) << 4)));
                cp_async16(abase + off, src, ok ? 16 : 0);
            }
        }
    };
    // B loader: phase j -> tap j%9, cb j/9; 128 rows x 128B into stage st
    auto load_B = [&](int j, int st) {
        const int cb = j / 9, tap = j - cb*9;
        const uint32_t sbase = sb + OFF_B + st * B_STAGE;
        #pragma unroll
        for (int k = 0; k < 4; k++) {
            int n = r0 + 32*k;
            const __half* src = g_wt + ((size_t)(tap*COUT + coBase + n))*CIN + cb*64 + jj*8;
            uint32_t off = (uint32_t)(n*128 + ((jj*16) ^ ((n & 7) << 4)));
            cp_async16(sbase + off, src, 16);
        }
    };

    float acc[4][4][4];
    #pragma unroll
    for (int mt = 0; mt < 4; mt++)
        #pragma unroll
        for (int nt = 0; nt < 4; nt++)
            #pragma unroll
            for (int q = 0; q < 4; q++) acc[mt][nt][q] = 0.f;

    // prologue: G1 = {A0, B0}; G2 = {B1}
    load_A(0, 0);
    load_B(0, 0);
    asm volatile("cp.async.commit_group;" ::: "memory");
    load_B(1, 1);
    asm volatile("cp.async.commit_group;" ::: "memory");

    // ldmatrix decompositions (round-8 proven mappings)
    const int rA  = (lane & 7) + ((lane >> 3) & 1) * 8;   // A: row-within-16
    const int hiA = (lane >> 4) << 4;                      // A: 16B k-half select
    const int rB  = ((lane >> 4) << 3) + (lane & 7);       // B: row-within-16
    const int khB = ((lane >> 3) & 1) << 4;                // B: 16B k-half select

    int stC = 0, stL = 2, bufA = 0;
    for (int j = 0; j < NPHASE; j++) {
        const int cb = j / 9, t = j - cb*9;
        const int dy = t / 3 - 1, dx = t - (t/3)*3 - 1;

        asm volatile("cp.async.wait_group 1;" ::: "memory");
        __syncthreads();
        if (j + 2 < NPHASE) load_B(j + 2, stL);
        if (t == 7 && cb + 1 < 8) load_A(cb + 1, bufA ^ 1);
        asm volatile("cp.async.commit_group;" ::: "memory");   // exactly 1 group/phase

        const uint32_t aBuf = sb + bufA * A_BUF_BYTES;
        const uint32_t sB   = sb + OFF_B + stC * B_STAGE;

        // per-fragment halo row base (lane row = base + rA folded in)
        int arow[4];
        #pragma unroll
        for (int mt = 0; mt < 4; mt++)
            arow[mt] = (wm*2 + (mt >> 1) + dy + 1)*34 + (mt & 1)*16 + dx + 1 + rA;

        #pragma unroll
        for (int ks = 0; ks < 4; ks++) {           // 4 k-steps of 16 halfs
            uint32_t a[4][4];
            #pragma unroll
            for (int mt = 0; mt < 4; mt++) {
                uint32_t kb = (uint32_t)(ks*32 + hiA);
                ldsm_x4(a[mt], aBuf + arow[mt]*128 + (kb ^ ((arow[mt] & 7) << 4)));
            }
            uint32_t bb[2][4];                     // [np]{rl/kh0, rl/kh1, rh/kh0, rh/kh1}
            #pragma unroll
            for (int np = 0; np < 2; np++) {
                int row = wn*32 + np*16 + rB;
                uint32_t kb = (uint32_t)(ks*32 + khB);
                ldsm_x4(bb[np], sB + row*128 + (kb ^ ((row & 7) << 4)));
            }
            #pragma unroll
            for (int nt = 0; nt < 4; nt++)
                #pragma unroll
                for (int mt = 0; mt < 4; mt++)
                    mma_f16(acc[mt][nt], a[mt], &bb[nt >> 1][(nt & 1) * 2]);
        }
        stC = (stC == 2) ? 0 : stC + 1;
        stL = (stL == 2) ? 0 : stL + 1;
        if (t == 8) bufA ^= 1;
    }

    __syncthreads();   // all compute done before spad overwrites smem

    // ---- epilogue: transpose via padded smem, coalesced stores ------------------
    float* spad = (float*)smem;                    // [128 n][129 m] floats (66KB)
    #pragma unroll
    for (int mt = 0; mt < 4; mt++)
        #pragma unroll
        for (int nt = 0; nt < 4; nt++) {
            int m0 = wm*64 + mt*16 + (lane >> 2);
            int n0 = wn*32 + nt*8 + 2*(lane & 3);
            spad[(n0    )*129 + m0    ] = acc[mt][nt][0];
            spad[(n0 + 1)*129 + m0    ] = acc[mt][nt][1];
            spad[(n0    )*129 + m0 + 8] = acc[mt][nt][2];
            spad[(n0 + 1)*129 + m0 + 8] = acc[mt][nt][3];
        }
    __syncthreads();
    {
        const float nsv = *ns_ptr;
        float nz[4];
        #pragma unroll
        for (int hh = 0; hh < 4; hh++)
            nz[hh] = noise[((size_t)b*RES + h0 + hh)*RES + g*PATCH + lane] * nsv;
        #pragma unroll
        for (int nn = 0; nn < 16; nn++) {
            int n  = wid*16 + nn;
            int co = coBase + n;
            float dm = g_demod[co], bs = bias[co];
            #pragma unroll
            for (int hh = 0; hh < 4; hh++) {
                float v = spad[n*129 + hh*32 + lane];
                v = v * dm + nz[hh] + bs;
                v = (v >= 0.f) ? v : 0.2f * v;
                out[(((size_t)(b*COUT + co))*RES + h0 + hh)*RES + g*PATCH + lane]
                    = v * 1.4142135623730951f;
            }
        }
    }
}

// ---------------- launch ---------------------------------------------------------
extern "C" void kernel_launch(void* const* d_in, const int* in_sizes, int n_in,
                              void* d_out, int out_size) {
    const float* x      = (const float*)d_in[0];
    const float* w      = (const float*)d_in[1];
    const float* wctx   = (const float*)d_in[2];
    const float* weight = (const float*)d_in[3];
    const float* aw     = (const float*)d_in[4];
    const float* ab     = (const float*)d_in[5];
    const float* bias   = (const float*)d_in[6];
    const float* ns     = (const float*)d_in[7];
    const float* noise  = (const float*)d_in[8];
    const int*   lb     = (const int*)d_in[9];
    float* out = (float*)d_out;

    cudaFuncSetAttribute(conv_kernel, cudaFuncAttributeMaxDynamicSharedMemorySize, CONV_SMEM);

    styles_kernel  <<<6, 256>>>(w, wctx, aw, ab);
    wtrans_kernel  <<<COUT, 256>>>(weight);
    std_kernel     <<<B*CIN*GRIDN, 256>>>(x);
    modulate_kernel<<<dim3(RES, CIN/32, B), 256>>>(x, lb);
    conv_kernel    <<<dim3(4, 1024), 256, CONV_SMEM>>>(noise, ns, bias, out);
}

// round 17
// speedup vs baseline: 1.0293x; 1.0094x over previous
#include <cuda_runtime.h>
#include <cuda_fp16.h>
#include <cstdint>

#define B      2
#define CIN    512
#define COUT   512
#define RES    256
#define WDIM   512
#define GRIDN  8
#define PATCH  32
#define NP     (B*GRIDN)

// ---------------- scratch (static device globals; no allocation) ----------------
__device__ __align__(128) __half g_xmt[(size_t)NP * RES * PATCH * CIN]; // [p][h][wp][c]
__device__ __align__(128) __half g_wt [(size_t)9 * COUT * CIN];         // [tap][cout][cin]
__device__ float g_styles[B * 3 * CIN];
__device__ float g_invstd[B * CIN * GRIDN];
__device__ float g_demod[COUT];

// ================= helpers ======================================================
__device__ __forceinline__ uint32_t smem_to_u32(const void* p) {
    uint32_t a;
    asm("{ .reg .u64 t; cvta.to.shared.u64 t, %1; cvt.u32.u64 %0, t; }" : "=r"(a) : "l"(p));
    return a;
}
__device__ __forceinline__ void cp_async16(uint32_t dst, const void* src, int sz) {
    asm volatile("cp.async.cg.shared.global [%0], [%1], 16, %2;"
                 :: "r"(dst), "l"(src), "r"(sz));
}
__device__ __forceinline__ void ldsm_x4(uint32_t* r, uint32_t addr) {
    asm volatile("ldmatrix.sync.aligned.m8n8.x4.shared.b16 {%0,%1,%2,%3}, [%4];"
                 : "=r"(r[0]), "=r"(r[1]), "=r"(r[2]), "=r"(r[3]) : "r"(addr));
}
__device__ __forceinline__ void mma_f16(float* d, const uint32_t* a, const uint32_t* b) {
    asm volatile("mma.sync.aligned.m16n8k16.row.col.f32.f16.f16.f32 "
                 "{%0,%1,%2,%3}, {%4,%5,%6,%7}, {%8,%9}, {%0,%1,%2,%3};"
                 : "+f"(d[0]), "+f"(d[1]), "+f"(d[2]), "+f"(d[3])
                 : "r"(a[0]), "r"(a[1]), "r"(a[2]), "r"(a[3]), "r"(b[0]), "r"(b[1]));
}

// ================= small kernels ================================================
__global__ void styles_kernel(const float* __restrict__ w, const float* __restrict__ wctx,
                              const float* __restrict__ aw, const float* __restrict__ ab) {
    int b = blockIdx.x / 3, s = blockIdx.x % 3;
    const float* src = (s == 0) ? (wctx + (b*2 + 0)*WDIM)
                     : (s == 1) ? (w + b*WDIM)
                                : (wctx + (b*2 + 1)*WDIM);
    __shared__ float sv[WDIM];
    for (int i = threadIdx.x; i < WDIM; i += blockDim.x) sv[i] = src[i];
    __syncthreads();
    for (int c = threadIdx.x; c < CIN; c += blockDim.x) {
        const float* row = aw + (size_t)c * WDIM;
        float acc = 0.f;
        #pragma unroll 8
        for (int d = 0; d < WDIM; d++) acc += sv[d] * row[d];
        g_styles[(b*3 + s)*CIN + c] = acc * 0.04419417382415922f + ab[c];
    }
}

// weight transform [cout][cin][9] -> [tap][cout][cin] (fp16) + fused demod
__global__ void wtrans_kernel(const float* __restrict__ wt) {
    __shared__ float sm[CIN * 9];
    __shared__ float red[256];
    int co = blockIdx.x, tid = threadIdx.x;
    const float* row = wt + (size_t)co * CIN * 9;
    float acc = 0.f;
    for (int i = tid; i < CIN * 9; i += 256) { float v = row[i]; sm[i] = v; acc += v * v; }
    red[tid] = acc;
    __syncthreads();
    for (int off = 128; off > 0; off >>= 1) {
        if (tid < off) red[tid] += red[tid + off];
        __syncthreads();
    }
    if (tid == 0) g_demod[co] = rsqrtf(red[0] + 1e-8f);
    for (int tap = 0; tap < 9; tap++)
        for (int ci = tid; ci < CIN; ci += 256)
            g_wt[((size_t)tap * COUT + co) * CIN + ci] = __float2half_rn(sm[ci * 9 + tap]);
}

// per-patch std (ddof=1) — warp-shuffle reduction
__global__ void std_kernel(const float* __restrict__ x) {
    int id = blockIdx.x;                    // ((b*512 + c)*8 + g)
    int g = id & 7, c = (id >> 3) & 511, b = id >> 12;
    const float* base = x + (((size_t)(b*CIN + c)) * RES) * RES + g * PATCH;
    int h = threadIdx.x;
    const float4* row = (const float4*)(base + (size_t)h * RES);
    float s = 0.f, q = 0.f;
    #pragma unroll
    for (int i = 0; i < PATCH/4; i++) {
        float4 v = row[i];
        s += v.x + v.y + v.z + v.w;
        q += v.x*v.x + v.y*v.y + v.z*v.z + v.w*v.w;
    }
    #pragma unroll
    for (int o = 16; o > 0; o >>= 1) {
        s += __shfl_xor_sync(0xFFFFFFFFu, s, o);
        q += __shfl_xor_sync(0xFFFFFFFFu, q, o);
    }
    __shared__ float ss[8], sq[8];
    if ((h & 31) == 0) { ss[h >> 5] = s; sq[h >> 5] = q; }
    __syncthreads();
    if (h == 0) {
        float S = 0.f, Q = 0.f;
        #pragma unroll
        for (int i = 0; i < 8; i++) { S += ss[i]; Q += sq[i]; }
        const float n = (float)(RES * PATCH);
        float var = (Q - S*S/n) / (n - 1.f);
        if (var < 0.f) var = 0.f;
        g_invstd[id] = 1.f / (sqrtf(var) + 1e-8f);
    }
}

// normalize + style lerp + transpose to [p][h][wp][c] (fp16)
// 32-channel blocks; x loads register-batched (16) for MLP
__global__ void modulate_kernel(const float* __restrict__ x, const int* __restrict__ lb) {
    __shared__ float sm[32][257];
    __shared__ float st_s[3][32];
    __shared__ float inv_s[32][8];
    int h = blockIdx.x, cc = blockIdx.y, b = blockIdx.z;
    int c0 = cc * 32;
    int tid = threadIdx.x;
    int w = tid;
    if (tid < 96) st_s[tid >> 5][tid & 31] = g_styles[(b*3 + (tid >> 5))*CIN + c0 + (tid & 31)];
    { int c = tid >> 3, gg = tid & 7;
      inv_s[c][gg] = g_invstd[(b*CIN + c0 + c)*GRIDN + gg]; }
    float center = (float)(lb[b] * PATCH);
    float t = ((float)w + 0.5f - center) * (1.f / 256.f);   // D = 256
    t = fminf(fmaxf(t, -1.f), 1.f);
    float a = fminf(fmaxf(-t, 0.f), 1.f);
    float r = fminf(fmaxf( t, 0.f), 1.f);
    float m = 1.f - a - r;
    int g = w >> 5;
    __syncthreads();
    const float* xrow = x + (((size_t)(b*CIN + c0)) * RES + h) * RES;
    #pragma unroll
    for (int half = 0; half < 2; half++) {
        float xv[16];
        #pragma unroll
        for (int i = 0; i < 16; i++)
            xv[i] = xrow[(size_t)(half*16 + i) * RES * RES + w];
        #pragma unroll
        for (int i = 0; i < 16; i++) {
            int c = half*16 + i;
            float sc = a * st_s[0][c] + m * st_s[1][c] + r * st_s[2][c];
            sm[c][w] = xv[i] * inv_s[c][g] * sc;
        }
    }
    __syncthreads();
    #pragma unroll
    for (int u = tid; u < 2048; u += 256) {
        int w2 = u >> 3, q = u & 7;
        int p = b*GRIDN + (w2 >> 5), wp = w2 & 31;
        __half2 o0 = __floats2half2_rn(sm[q*4+0][w2], sm[q*4+1][w2]);
        __half2 o1 = __floats2half2_rn(sm[q*4+2][w2], sm[q*4+3][w2]);
        uint2 pk = make_uint2(*(uint32_t*)&o0, *(uint32_t*)&o1);
        *(uint2*)(g_xmt + ((((size_t)p * RES + h)) * PATCH + wp) * CIN + c0 + q*4) = pk;
    }
}

// ================= fp16 mma.sync conv (A-halo reuse across taps) =================
// CTA: 128 M (4h x 32wp) x 128 N (cout); 256 thr = 2x4 warps of 64x32
// Outer: 8 cin-blocks of 64; per cb ONE haloed A tile (6h x 34w) serves all 9 taps.
// A double-buffered (2 x 26KB), B triple-buffered (3 x 16KB); 2 CTAs/SM.
#define A_BUF_BYTES 26624          // 208 rows x 128B (204 used)
#define OFF_B       53248          // after 2 A buffers
#define B_STAGE     16384
#define CONV_SMEM   102400
#define NPHASE      72             // 8 cb x 9 taps

__global__ __launch_bounds__(256, 2) void conv_kernel(
    const float* __restrict__ noise, const float* __restrict__ ns_ptr,
    const float* __restrict__ bias,  float* __restrict__ out)
{
    extern __shared__ __align__(1024) char smem[];
    const uint32_t sb = smem_to_u32(smem);
    const int tid  = threadIdx.x;
    const int wid  = tid >> 5, lane = tid & 31;
    const int wm   = wid & 1,  wn   = wid >> 1;   // 2x4 warp grid (64m x 32n tiles)
    const int sIdx = blockIdx.y;                  // 0..1023
    const int p    = sIdx >> 6, hblk = sIdx & 63;
    const int h0   = hblk * 4;
    const int b    = p >> 3, g = p & 7;
    const int coBase = blockIdx.x * 128;

    const __half* xm_p = g_xmt + (size_t)p * RES * PATCH * CIN;
    const int jj = tid & 7;                        // 16B column (8 halfs)
    const int r0 = tid >> 3;                       // 0..31

    // A halo loader: 204 rows = 6 hs x 34 ws, 128B each (64 cin)
    auto load_A = [&](int cb, int buf) {
        const uint32_t abase = sb + buf * A_BUF_BYTES;
        #pragma unroll
        for (int it = 0; it < 7; it++) {
            int rr = r0 + 32*it;
            if (rr < 204) {
                int hh = rr / 34, ww = rr - hh*34;
                int hs = h0 - 1 + hh, ws = ww - 1;
                bool ok = ((unsigned)hs < 256u) && ((unsigned)ws < 32u);
                const __half* src = xm_p + (ok ? (((size_t)hs*PATCH + ws)*CIN + cb*64 + jj*8) : 0);
                uint32_t off = (uint32_t)(rr*128 + ((jj*16) ^ ((rr & 7) << 4)));
                cp_async16(abase + off, src, ok ? 16 : 0);
            }
        }
    };
    // B loader: phase j -> tap j%9, cb j/9; 128 rows x 128B into stage st
    auto load_B = [&](int j, int st) {
        const int cb = j / 9, tap = j - cb*9;
        const uint32_t sbase = sb + OFF_B + st * B_STAGE;
        #pragma unroll
        for (int k = 0; k < 4; k++) {
            int n = r0 + 32*k;
            const __half* src = g_wt + ((size_t)(tap*COUT + coBase + n))*CIN + cb*64 + jj*8;
            uint32_t off = (uint32_t)(n*128 + ((jj*16) ^ ((n & 7) << 4)));
            cp_async16(sbase + off, src, 16);
        }
    };

    float acc[4][4][4];
    #pragma unroll
    for (int mt = 0; mt < 4; mt++)
        #pragma unroll
        for (int nt = 0; nt < 4; nt++)
            #pragma unroll
            for (int q = 0; q < 4; q++) acc[mt][nt][q] = 0.f;

    // prologue: G1 = {A0, B0}; G2 = {B1}
    load_A(0, 0);
    load_B(0, 0);
    asm volatile("cp.async.commit_group;" ::: "memory");
    load_B(1, 1);
    asm volatile("cp.async.commit_group;" ::: "memory");

    // ldmatrix decompositions (round-8 proven mappings)
    const int rA  = (lane & 7) + ((lane >> 3) & 1) * 8;   // A: row-within-16
    const int hiA = (lane >> 4) << 4;                      // A: 16B k-half select
    const int rB  = ((lane >> 4) << 3) + (lane & 7);       // B: row-within-16
    const int khB = ((lane >> 3) & 1) << 4;                // B: 16B k-half select

    int stC = 0, stL = 2, bufA = 0;
    for (int j = 0; j < NPHASE; j++) {
        const int cb = j / 9, t = j - cb*9;
        const int dy = t / 3 - 1, dx = t - (t/3)*3 - 1;

        asm volatile("cp.async.wait_group 1;" ::: "memory");
        __syncthreads();
        if (j + 2 < NPHASE) load_B(j + 2, stL);
        if (t == 7 && cb + 1 < 8) load_A(cb + 1, bufA ^ 1);
        asm volatile("cp.async.commit_group;" ::: "memory");   // exactly 1 group/phase

        const uint32_t aBuf = sb + bufA * A_BUF_BYTES;
        const uint32_t sB   = sb + OFF_B + stC * B_STAGE;

        // per-fragment halo row base (lane row = base + rA folded in)
        int arow[4];
        #pragma unroll
        for (int mt = 0; mt < 4; mt++)
            arow[mt] = (wm*2 + (mt >> 1) + dy + 1)*34 + (mt & 1)*16 + dx + 1 + rA;

        #pragma unroll
        for (int ks = 0; ks < 4; ks++) {           // 4 k-steps of 16 halfs
            uint32_t a[4][4];
            #pragma unroll
            for (int mt = 0; mt < 4; mt++) {
                uint32_t kb = (uint32_t)(ks*32 + hiA);
                ldsm_x4(a[mt], aBuf + arow[mt]*128 + (kb ^ ((arow[mt] & 7) << 4)));
            }
            uint32_t bb[2][4];                     // [np]{rl/kh0, rl/kh1, rh/kh0, rh/kh1}
            #pragma unroll
            for (int np = 0; np < 2; np++) {
                int row = wn*32 + np*16 + rB;
                uint32_t kb = (uint32_t)(ks*32 + khB);
                ldsm_x4(bb[np], sB + row*128 + (kb ^ ((row & 7) << 4)));
            }
            #pragma unroll
            for (int nt = 0; nt < 4; nt++)
                #pragma unroll
                for (int mt = 0; mt < 4; mt++)
                    mma_f16(acc[mt][nt], a[mt], &bb[nt >> 1][(nt & 1) * 2]);
        }
        stC = (stC == 2) ? 0 : stC + 1;
        stL = (stL == 2) ? 0 : stL + 1;
        if (t == 8) bufA ^= 1;
    }

    __syncthreads();   // all compute done before spad overwrites smem

    // ---- epilogue: transpose via padded smem, coalesced stores ------------------
    float* spad = (float*)smem;                    // [128 n][129 m] floats (66KB)
    #pragma unroll
    for (int mt = 0; mt < 4; mt++)
        #pragma unroll
        for (int nt = 0; nt < 4; nt++) {
            int m0 = wm*64 + mt*16 + (lane >> 2);
            int n0 = wn*32 + nt*8 + 2*(lane & 3);
            spad[(n0    )*129 + m0    ] = acc[mt][nt][0];
            spad[(n0 + 1)*129 + m0    ] = acc[mt][nt][1];
            spad[(n0    )*129 + m0 + 8] = acc[mt][nt][2];
            spad[(n0 + 1)*129 + m0 + 8] = acc[mt][nt][3];
        }
    __syncthreads();
    {
        const float nsv = *ns_ptr;
        float nz[4];
        #pragma unroll
        for (int hh = 0; hh < 4; hh++)
            nz[hh] = noise[((size_t)b*RES + h0 + hh)*RES + g*PATCH + lane] * nsv;
        #pragma unroll
        for (int nn = 0; nn < 16; nn++) {
            int n  = wid*16 + nn;
            int co = coBase + n;
            float dm = g_demod[co], bs = bias[co];
            #pragma unroll
            for (int hh = 0; hh < 4; hh++) {
                float v = spad[n*129 + hh*32 + lane];
                v = v * dm + nz[hh] + bs;
                v = (v >= 0.f) ? v : 0.2f * v;
                out[(((size_t)(b*COUT + co))*RES + h0 + hh)*RES + g*PATCH + lane]
                    = v * 1.4142135623730951f;
            }
        }
    }
}

// ---------------- launch: wtrans forked onto a side stream inside capture --------
extern "C" void kernel_launch(void* const* d_in, const int* in_sizes, int n_in,
                              void* d_out, int out_size) {
    const float* x      = (const float*)d_in[0];
    const float* w      = (const float*)d_in[1];
    const float* wctx   = (const float*)d_in[2];
    const float* weight = (const float*)d_in[3];
    const float* aw     = (const float*)d_in[4];
    const float* ab     = (const float*)d_in[5];
    const float* bias   = (const float*)d_in[6];
    const float* ns     = (const float*)d_in[7];
    const float* noise  = (const float*)d_in[8];
    const int*   lb     = (const int*)d_in[9];
    float* out = (float*)d_out;

    cudaFuncSetAttribute(conv_kernel, cudaFuncAttributeMaxDynamicSharedMemorySize, CONV_SMEM);

    cudaStream_t s1;
    cudaEvent_t eFork, eJoin;
    cudaStreamCreateWithFlags(&s1, cudaStreamNonBlocking);
    cudaEventCreateWithFlags(&eFork, cudaEventDisableTiming);
    cudaEventCreateWithFlags(&eJoin, cudaEventDisableTiming);

    // fork: wtrans (independent of x-path) runs concurrently with styles/std/modulate
    cudaEventRecord(eFork, 0);
    cudaStreamWaitEvent(s1, eFork, 0);
    wtrans_kernel  <<<COUT, 256, 0, s1>>>(weight);

    styles_kernel  <<<6, 256>>>(w, wctx, aw, ab);
    std_kernel     <<<B*CIN*GRIDN, 256>>>(x);
    modulate_kernel<<<dim3(RES, CIN/32, B), 256>>>(x, lb);

    // join: conv needs both g_xmt (main) and g_wt/g_demod (s1)
    cudaEventRecord(eJoin, s1);
    cudaStreamWaitEvent(0, eJoin, 0);
    conv_kernel    <<<dim3(4, 1024), 256, CONV_SMEM>>>(noise, ns, bias, out);

    cudaEventDestroy(eFork);
    cudaEventDestroy(eJoin);
    cudaStreamDestroy(s1);
}